// round 6
// baseline (speedup 1.0000x reference)
#include <cuda_runtime.h>

// BilateralFilter: x [32, 3, 64, 512] f32 -> out [32, 4, 14, 64, 512] f32
// out[b, cls, k, z, a] = exp(-sqdist(b,k,z,a) * inv2theta2[cls])
// inv2theta2 = [2222.2222, 2222.2222, 5000, 5000]; 5000 = 2.25 * 2222.2222.
//
// R6: smem staging. A 256-thread block covers 2 full z-rows; it stages the 12
// input rows it needs (3ch x 4z, zero-padded 4 floats each end) into smem with
// 6 LDG.128/thread, then reads windows via conflict-free LDS.128.
// Replaces 45 LDG/thread (R4) -> 6; eliminates all a-boundary predication.
// Targets the L1tex bottleneck ncu showed (59.7% vs DRAM 55.3%).

#define BZ 32
#define ZZ 64
#define AA 512
#define PLANE (ZZ * AA)          // 32768
#define RP 520                   // 4 pad + 512 + 4 pad floats per staged row

__global__ __launch_bounds__(256, 4)
void bilateral_kernel(const float* __restrict__ x, float* __restrict__ out) {
    __shared__ float s[12 * RP]; // [ch*4 + zr][RP], 24,960 B

    const int B = blockIdx.x;
    const int t = threadIdx.x;
    const int b = B >> 5;                // 32 blocks per batch
    const int zbase = (B & 31) << 1;     // block covers z = zbase, zbase+1

    // Zero the 4-float pads at both ends of each of the 12 rows.
    if (t < 12) {
        const float4 z4 = make_float4(0.f, 0.f, 0.f, 0.f);
        *reinterpret_cast<float4*>(&s[t * RP])          = z4;
        *reinterpret_cast<float4*>(&s[t * RP + 4 + AA]) = z4;
    }
    // Cooperative stage: 12 rows x 128 float4 = 1536 float4, 6 per thread.
#pragma unroll
    for (int i = 0; i < 6; i++) {
        int idx  = t + i * 256;          // 0..1535
        int row  = idx >> 7;             // 0..11 = ch*4 + zr
        int col4 = idx & 127;
        int ch   = row >> 2;
        int zr   = row & 3;
        int zsrc = zbase - 1 + zr;
        float4 v = make_float4(0.f, 0.f, 0.f, 0.f);
        if ((unsigned)zsrc < ZZ)
            v = *reinterpret_cast<const float4*>(
                x + ((b * 3 + ch) * PLANE) + (zsrc << 9) + (col4 << 2));
        *reinterpret_cast<float4*>(&s[row * RP + 4 + (col4 << 2)]) = v;
    }
    __syncthreads();

    const int a4   = t & 127;
    const int zloc = t >> 7;             // 0 or 1
    const int a0   = a4 << 2;
    const int z    = zbase + zloc;
    const float C1 = 2222.2222f;         // 1/(2*0.015^2); 5000 = 2.25*C1

    // Center quads per channel: smem row ch*4 + (1+zloc), logical col a0.
    float c0[3], c1[3], c2[3], c3[3];
#pragma unroll
    for (int ch = 0; ch < 3; ch++) {
        float4 v = *reinterpret_cast<float4*>(
            &s[(ch * 4 + 1 + zloc) * RP + 4 + a0]);
        c0[ch] = v.x; c1[ch] = v.y; c2[ch] = v.z; c3[ch] = v.w;
    }

    float* ob = out + (size_t)b * (4 * 14 * PLANE) + (z << 9) + a0;
    int k = 0;

#pragma unroll
    for (int dz = 0; dz < 3; dz++) {
        // sq[da][pixel]: accumulate over channels with a small live set.
        float sq[5][4];
#pragma unroll
        for (int da = 0; da < 5; da++)
#pragma unroll
            for (int j = 0; j < 4; j++) sq[da][j] = 0.f;

#pragma unroll
        for (int ch = 0; ch < 3; ch++) {
            // Padded indices a0..a0+11 = logical cols a0-4..a0+7.
            float* p = &s[(ch * 4 + zloc + dz) * RP + a0];
            float4 wa = *reinterpret_cast<float4*>(p);
            float4 wb = *reinterpret_cast<float4*>(p + 4);
            float4 wc = *reinterpret_cast<float4*>(p + 8);
            float w[12] = {wa.x, wa.y, wa.z, wa.w,
                           wb.x, wb.y, wb.z, wb.w,
                           wc.x, wc.y, wc.z, wc.w};
            float cc[4] = {c0[ch], c1[ch], c2[ch], c3[ch]};
#pragma unroll
            for (int da = 0; da < 5; da++) {
#pragma unroll
                for (int j = 0; j < 4; j++) {
                    // pixel col a0+j, neighbor col a0+j+da-2 -> w[j+da+2]
                    float d = cc[j] - w[j + da + 2];
                    sq[da][j] += d * d;
                }
            }
        }

#pragma unroll
        for (int da = 0; da < 5; da++) {
            if (dz == 1 && da == 2) continue;   // center excluded

            float t0 = -C1 * sq[da][0], t1 = -C1 * sq[da][1];
            float t2 = -C1 * sq[da][2], t3 = -C1 * sq[da][3];
            float tmax = fmaxf(fmaxf(t0, t1), fmaxf(t2, t3));
            float4 e1 = make_float4(0.f, 0.f, 0.f, 0.f);
            float4 e2 = make_float4(0.f, 0.f, 0.f, 0.f);
            // expf underflows below ~-87.3; ~88% of warp-iterations skip MUFU.
            if (tmax > -88.0f) {
                e1.x = __expf(t0);          e1.y = __expf(t1);
                e1.z = __expf(t2);          e1.w = __expf(t3);
                e2.x = __expf(2.25f * t0);  e2.y = __expf(2.25f * t1);
                e2.z = __expf(2.25f * t2);  e2.w = __expf(2.25f * t3);
            }
            float* p = ob + k * PLANE;
            __stcs(reinterpret_cast<float4*>(p),              e1);  // class 0
            __stcs(reinterpret_cast<float4*>(p + 14 * PLANE), e1);  // class 1
            __stcs(reinterpret_cast<float4*>(p + 28 * PLANE), e2);  // class 2
            __stcs(reinterpret_cast<float4*>(p + 42 * PLANE), e2);  // class 3
            k++;
        }
    }
}

extern "C" void kernel_launch(void* const* d_in, const int* in_sizes, int n_in,
                              void* d_out, int out_size) {
    const float* x = (const float*)d_in[0];
    float* out = (float*)d_out;
    int blocks = BZ * (ZZ / 2);          // 1024 blocks x 256 threads
    bilateral_kernel<<<blocks, 256>>>(x, out);
}